// round 3
// baseline (speedup 1.0000x reference)
#include <cuda_runtime.h>

// Problem constants (fixed: B=65536, T=100, D_CP=2, D_FIN=3, HID=12, D_OUT=2)
#define BT_B 65536
#define BT_T 100

typedef unsigned long long u64;

__device__ __forceinline__ u64 pack2(float lo, float hi) {
    u64 r; asm("mov.b64 %0, {%1, %2};" : "=l"(r) : "f"(lo), "f"(hi)); return r;
}
__device__ __forceinline__ void unpack2(u64 v, float& lo, float& hi) {
    asm("mov.b64 {%0, %1}, %2;" : "=f"(lo), "=f"(hi) : "l"(v));
}
__device__ __forceinline__ u64 fma2(u64 a, u64 b, u64 c) {
    u64 d; asm("fma.rn.f32x2 %0, %1, %2, %3;" : "=l"(d) : "l"(a), "l"(b), "l"(c)); return d;
}
__device__ __forceinline__ u64 add2(u64 a, u64 b) {
    u64 d; asm("add.rn.f32x2 %0, %1, %2;" : "=l"(d) : "l"(a), "l"(b)); return d;
}
__device__ __forceinline__ float tanhapx(float x) {
    float r; asm("tanh.approx.f32 %0, %1;" : "=f"(r) : "f"(x)); return r;
}

// One recurrence step for a single row, everything register-resident.
// State: (u, v) with o = (c0+u, c1+v).  a[j] = base[j] + fin@Wr[2:5] + u*Wr0[j] + v*Wr1[j]
struct RowStep {
    __device__ __forceinline__ static void run(
        float& u, float& v,
        float x2, float x3, float x4,
        const u64 (&Wp)[5][6], const u64 (&Wo0p)[6], const u64 (&Wo1p)[6],
        const u64 (&base)[6])
    {
        // Off-chain partial: base + x2*Wr2 + x3*Wr3 + x4*Wr4 (independent of u,v)
        u64 px2 = pack2(x2, x2), px3 = pack2(x3, x3), px4 = pack2(x4, x4);
        u64 part[6];
        #pragma unroll
        for (int k = 0; k < 6; k++)
            part[k] = fma2(px4, Wp[4][k], fma2(px3, Wp[3][k], fma2(px2, Wp[2][k], base[k])));

        // Critical chain: + u*Wr0 + v*Wr1
        u64 pu = pack2(u, u), pv = pack2(v, v);
        float h[12];
        #pragma unroll
        for (int k = 0; k < 6; k++) {
            u64 a = fma2(pv, Wp[1][k], fma2(pu, Wp[0][k], part[k]));
            float a0, a1;
            unpack2(a, a0, a1);
            h[2 * k + 0] = tanhapx(a0);
            h[2 * k + 1] = tanhapx(a1);
        }

        // u = h . Wo[:,0], v = h . Wo[:,1] — packed dots, split accumulators
        u64 hp[6];
        #pragma unroll
        for (int k = 0; k < 6; k++) hp[k] = pack2(h[2 * k], h[2 * k + 1]);

        u64 ua = fma2(hp[0], Wo0p[0], 0ull), ub = fma2(hp[1], Wo0p[1], 0ull);
        u64 va = fma2(hp[0], Wo1p[0], 0ull), vb = fma2(hp[1], Wo1p[1], 0ull);
        #pragma unroll
        for (int k = 2; k < 6; k += 2) {
            ua = fma2(hp[k],     Wo0p[k],     ua);
            ub = fma2(hp[k + 1], Wo0p[k + 1], ub);
            va = fma2(hp[k],     Wo1p[k],     va);
            vb = fma2(hp[k + 1], Wo1p[k + 1], vb);
        }
        u64 us = add2(ua, ub), vs = add2(va, vb);
        float ul, uh, vl, vh;
        unpack2(us, ul, uh);
        unpack2(vs, vl, vh);
        u = ul + uh;
        v = vl + vh;
    }
};

__global__ __launch_bounds__(128, 2)
void deform_tracker_kernel(const float* __restrict__ cp,     // (B, T, 2)
                           const float* __restrict__ fin,    // (B, T, 3)
                           const float* __restrict__ Wr,     // (5, 12)
                           const float* __restrict__ br,     // (12,)
                           const float* __restrict__ Wo,     // (14, 2)
                           const float* __restrict__ bo,     // (2,)
                           float* __restrict__ out)          // (B, T, 2)
{
    const int t = blockIdx.x * blockDim.x + threadIdx.x;   // 0..32767
    const int bA = t;
    const int bB = t + BT_B / 2;

    // ---- Weights, fully register-resident (packed over hidden-dim pairs) ----
    u64 Wp[5][6];
    #pragma unroll
    for (int i = 0; i < 5; i++)
        #pragma unroll
        for (int k = 0; k < 6; k++)
            Wp[i][k] = pack2(__ldg(Wr + i * 12 + 2 * k), __ldg(Wr + i * 12 + 2 * k + 1));

    u64 Wo0p[6], Wo1p[6];
    #pragma unroll
    for (int k = 0; k < 6; k++) {
        Wo0p[k] = pack2(__ldg(Wo + (2 + 2 * k) * 2 + 0), __ldg(Wo + (3 + 2 * k) * 2 + 0));
        Wo1p[k] = pack2(__ldg(Wo + (2 + 2 * k) * 2 + 1), __ldg(Wo + (3 + 2 * k) * 2 + 1));
    }
    const float w00 = __ldg(Wo + 0), w01 = __ldg(Wo + 1);
    const float w10 = __ldg(Wo + 2), w11 = __ldg(Wo + 3);
    const float bo0 = __ldg(bo + 0), bo1 = __ldg(bo + 1);

    // ---- Per-row invariants ----
    const float2 cpA = *reinterpret_cast<const float2*>(cp + (size_t)bA * (BT_T * 2));
    const float2 cpB = *reinterpret_cast<const float2*>(cp + (size_t)bB * (BT_T * 2));

    const float cA0 = fmaf(cpA.x, w00, fmaf(cpA.y, w10, bo0));
    const float cA1 = fmaf(cpA.x, w01, fmaf(cpA.y, w11, bo1));
    const float cB0 = fmaf(cpB.x, w00, fmaf(cpB.y, w10, bo0));
    const float cB1 = fmaf(cpB.x, w01, fmaf(cpB.y, w11, bo1));

    // base[j] = br[j] + c0*Wr0[j] + c1*Wr1[j]
    u64 baseA[6], baseB[6];
    {
        u64 pA0 = pack2(cA0, cA0), pA1 = pack2(cA1, cA1);
        u64 pB0 = pack2(cB0, cB0), pB1 = pack2(cB1, cB1);
        #pragma unroll
        for (int k = 0; k < 6; k++) {
            u64 brp = pack2(__ldg(br + 2 * k), __ldg(br + 2 * k + 1));
            baseA[k] = fma2(pA1, Wp[1][k], fma2(pA0, Wp[0][k], brp));
            baseB[k] = fma2(pB1, Wp[1][k], fma2(pB0, Wp[0][k], brp));
        }
    }

    float uA = cpA.x - cA0, vA = cpA.y - cA1;
    float uB = cpB.x - cB0, vB = cpB.y - cB1;

    const float4* fpA = reinterpret_cast<const float4*>(fin + (size_t)bA * (BT_T * 3));
    const float4* fpB = reinterpret_cast<const float4*>(fin + (size_t)bB * (BT_T * 3));
    float4* opA = reinterpret_cast<float4*>(out + (size_t)bA * (BT_T * 2));
    float4* opB = reinterpret_cast<float4*>(out + (size_t)bB * (BT_T * 2));

    #pragma unroll 1
    for (int c = 0; c < BT_T / 4; c++) {
        float4 a0 = fpA[3 * c + 0], a1 = fpA[3 * c + 1], a2 = fpA[3 * c + 2];
        float4 e0 = fpB[3 * c + 0], e1 = fpB[3 * c + 1], e2 = fpB[3 * c + 2];
        float fA[12] = {a0.x, a0.y, a0.z, a0.w, a1.x, a1.y, a1.z, a1.w, a2.x, a2.y, a2.z, a2.w};
        float fB[12] = {e0.x, e0.y, e0.z, e0.w, e1.x, e1.y, e1.z, e1.w, e2.x, e2.y, e2.z, e2.w};
        float rA[8], rB[8];

        #pragma unroll
        for (int s = 0; s < 4; s++) {
            RowStep::run(uA, vA, fA[3 * s], fA[3 * s + 1], fA[3 * s + 2], Wp, Wo0p, Wo1p, baseA);
            RowStep::run(uB, vB, fB[3 * s], fB[3 * s + 1], fB[3 * s + 2], Wp, Wo0p, Wo1p, baseB);
            rA[2 * s + 0] = cA0 + uA;
            rA[2 * s + 1] = cA1 + vA;
            rB[2 * s + 0] = cB0 + uB;
            rB[2 * s + 1] = cB1 + vB;
        }

        opA[2 * c + 0] = make_float4(rA[0], rA[1], rA[2], rA[3]);
        opA[2 * c + 1] = make_float4(rA[4], rA[5], rA[6], rA[7]);
        opB[2 * c + 0] = make_float4(rB[0], rB[1], rB[2], rB[3]);
        opB[2 * c + 1] = make_float4(rB[4], rB[5], rB[6], rB[7]);
    }
}

extern "C" void kernel_launch(void* const* d_in, const int* in_sizes, int n_in,
                              void* d_out, int out_size) {
    const float* cp  = (const float*)d_in[0];  // control_point_input (B,T,2)
    const float* fin = (const float*)d_in[1];  // finger_input (B,T,3)
    const float* Wr  = (const float*)d_in[2];  // W_rnn (5,12)
    // d_in[3] = U_rnn — mathematically inert
    const float* br  = (const float*)d_in[4];  // b_rnn (12,)
    const float* Wo  = (const float*)d_in[5];  // W_out (14,2)
    const float* bo  = (const float*)d_in[6];  // b_out (2,)
    float* out = (float*)d_out;

    const int threads = 128;
    const int total = BT_B / 2;                 // 2 rows per thread
    const int blocks = total / threads;         // 256
    deform_tracker_kernel<<<blocks, threads>>>(cp, fin, Wr, br, Wo, bo, out);
}

// round 4
// speedup vs baseline: 1.1300x; 1.1300x over previous
#include <cuda_runtime.h>

// Problem constants (fixed: B=65536, T=100, D_CP=2, D_FIN=3, HID=12, D_OUT=2)
#define BT_B 65536
#define BT_T 100

typedef unsigned long long u64;

__device__ __forceinline__ u64 pack2(float lo, float hi) {
    u64 r; asm("mov.b64 %0, {%1, %2};" : "=l"(r) : "f"(lo), "f"(hi)); return r;
}
__device__ __forceinline__ void unpack2(u64 v, float& lo, float& hi) {
    asm("mov.b64 {%0, %1}, %2;" : "=f"(lo), "=f"(hi) : "l"(v));
}
__device__ __forceinline__ u64 fma2(u64 a, u64 b, u64 c) {
    u64 d; asm("fma.rn.f32x2 %0, %1, %2, %3;" : "=l"(d) : "l"(a), "l"(b), "l"(c)); return d;
}
__device__ __forceinline__ float tanhapx(float x) {
    float r; asm("tanh.approx.f32 %0, %1;" : "=f"(r) : "f"(x)); return r;
}

// Two threads cooperate on one batch row. Thread half h∈{0,1} owns hidden units
// [6h, 6h+6). Partial output dots are exchanged with shfl.xor(1); both threads
// then hold the full (u,v) state and stay in lockstep (identical fp ops).
__global__ __launch_bounds__(128, 6)
void deform_tracker_kernel(const float* __restrict__ cp,     // (B, T, 2)
                           const float* __restrict__ fin,    // (B, T, 3)
                           const float* __restrict__ Wr,     // (5, 12)
                           const float* __restrict__ br,     // (12,)
                           const float* __restrict__ Wo,     // (14, 2)
                           const float* __restrict__ bo,     // (2,)
                           float* __restrict__ out)          // (B, T, 2)
{
    const int gt   = blockIdx.x * blockDim.x + threadIdx.x;  // 0 .. 131071
    const int row  = gt >> 1;
    const int half = gt & 1;                                  // which 6 hidden units
    const int cbase = 6 * half;                               // first owned column

    // ---- Per-thread register-resident weights (own half of the hidden dim) ----
    // RNN kernel: 5 inputs x 3 packed pairs
    u64 Wp[5][3];
    #pragma unroll
    for (int i = 0; i < 5; i++)
        #pragma unroll
        for (int k = 0; k < 3; k++)
            Wp[i][k] = pack2(__ldg(Wr + i * 12 + cbase + 2 * k),
                             __ldg(Wr + i * 12 + cbase + 2 * k + 1));

    // Output weights for own h's: scalar (u-col and v-col)
    float wu[6], wv[6];
    #pragma unroll
    for (int j = 0; j < 6; j++) {
        wu[j] = __ldg(Wo + (2 + cbase + j) * 2 + 0);
        wv[j] = __ldg(Wo + (2 + cbase + j) * 2 + 1);
    }
    // cp0-part of W_out + biases (needed by both threads)
    const float w00 = __ldg(Wo + 0), w01 = __ldg(Wo + 1);
    const float w10 = __ldg(Wo + 2), w11 = __ldg(Wo + 3);
    const float bo0 = __ldg(bo + 0), bo1 = __ldg(bo + 1);

    // ---- Per-row invariants ----
    const float2 cp0 = *reinterpret_cast<const float2*>(cp + (size_t)row * (BT_T * 2));
    const float c0 = fmaf(cp0.x, w00, fmaf(cp0.y, w10, bo0));
    const float c1 = fmaf(cp0.x, w01, fmaf(cp0.y, w11, bo1));

    // base[k] = br + c0*Wr0 + c1*Wr1  (folds the constant part of the input o = (c0+u, c1+v))
    u64 base[3];
    {
        u64 p0 = pack2(c0, c0), p1 = pack2(c1, c1);
        #pragma unroll
        for (int k = 0; k < 3; k++) {
            u64 brp = pack2(__ldg(br + cbase + 2 * k), __ldg(br + cbase + 2 * k + 1));
            base[k] = fma2(p1, Wp[1][k], fma2(p0, Wp[0][k], brp));
        }
    }

    float u = cp0.x - c0, v = cp0.y - c1;    // o = (c0+u, c1+v); o_init = cp0

    const float4* fp = reinterpret_cast<const float4*>(fin + (size_t)row * (BT_T * 3));
    float4* op = reinterpret_cast<float4*>(out + (size_t)row * (BT_T * 2));

    #pragma unroll 1
    for (int c = 0; c < BT_T / 4; c++) {
        float4 fa = fp[3 * c + 0];
        float4 fb = fp[3 * c + 1];
        float4 fc = fp[3 * c + 2];
        float f[12] = {fa.x, fa.y, fa.z, fa.w,
                       fb.x, fb.y, fb.z, fb.w,
                       fc.x, fc.y, fc.z, fc.w};
        float res[8];

        #pragma unroll
        for (int s = 0; s < 4; s++) {
            // Off-chain partial (independent of u,v): base + fin_t @ Wr[2:5]
            u64 px2 = pack2(f[3 * s + 0], f[3 * s + 0]);
            u64 px3 = pack2(f[3 * s + 1], f[3 * s + 1]);
            u64 px4 = pack2(f[3 * s + 2], f[3 * s + 2]);
            u64 part[3];
            #pragma unroll
            for (int k = 0; k < 3; k++)
                part[k] = fma2(px4, Wp[4][k], fma2(px3, Wp[3][k], fma2(px2, Wp[2][k], base[k])));

            // Critical chain: add u,v contribution, tanh
            u64 pu = pack2(u, u), pv = pack2(v, v);
            float h[6];
            #pragma unroll
            for (int k = 0; k < 3; k++) {
                u64 a = fma2(pv, Wp[1][k], fma2(pu, Wp[0][k], part[k]));
                float a0, a1;
                unpack2(a, a0, a1);
                h[2 * k + 0] = tanhapx(a0);
                h[2 * k + 1] = tanhapx(a1);
            }

            // Own half of the output dot (split accumulators, depth 3)
            float ua = h[0] * wu[0], ub = h[1] * wu[1];
            float va = h[0] * wv[0], vb = h[1] * wv[1];
            #pragma unroll
            for (int j = 2; j < 6; j += 2) {
                ua = fmaf(h[j],     wu[j],     ua);
                ub = fmaf(h[j + 1], wu[j + 1], ub);
                va = fmaf(h[j],     wv[j],     va);
                vb = fmaf(h[j + 1], wv[j + 1], vb);
            }
            float uo = ua + ub, vo = va + vb;

            // Exchange partner's partial; both threads now hold full (u,v)
            float up = __shfl_xor_sync(0xFFFFFFFFu, uo, 1);
            float vp = __shfl_xor_sync(0xFFFFFFFFu, vo, 1);
            u = uo + up;
            v = vo + vp;

            res[2 * s + 0] = c0 + u;
            res[2 * s + 1] = c1 + v;
        }

        if (half == 0) {
            op[2 * c + 0] = make_float4(res[0], res[1], res[2], res[3]);
            op[2 * c + 1] = make_float4(res[4], res[5], res[6], res[7]);
        }
    }
}

extern "C" void kernel_launch(void* const* d_in, const int* in_sizes, int n_in,
                              void* d_out, int out_size) {
    const float* cp  = (const float*)d_in[0];  // control_point_input (B,T,2)
    const float* fin = (const float*)d_in[1];  // finger_input (B,T,3)
    const float* Wr  = (const float*)d_in[2];  // W_rnn (5,12)
    // d_in[3] = U_rnn — mathematically inert (hidden state reset each step)
    const float* br  = (const float*)d_in[4];  // b_rnn (12,)
    const float* Wo  = (const float*)d_in[5];  // W_out (14,2)
    const float* bo  = (const float*)d_in[6];  // b_out (2,)
    float* out = (float*)d_out;

    const int threads = 128;
    const int total = BT_B * 2;                 // 2 threads per row
    const int blocks = total / threads;         // 1024
    deform_tracker_kernel<<<blocks, threads>>>(cp, fin, Wr, br, Wo, bo, out);
}